// round 5
// baseline (speedup 1.0000x reference)
#include <cuda_runtime.h>
#include <cuda_bf16.h>
#include <cstdint>
#include <math.h>

#define B_   2
#define T_   2048
#define C_   1024
#define NH_  16
#define HS_  64
#define WIN_ 256

// ---------------------------------------------------------------------------
// Scratch (__device__ globals; no allocation allowed)
// ---------------------------------------------------------------------------
__device__ __nv_bfloat16 g_qkvh[(size_t)B_ * T_ * 3 * C_];   // split qkv hi
__device__ __nv_bfloat16 g_qkvl[(size_t)B_ * T_ * 3 * C_];   // split qkv lo
__device__ __nv_bfloat16 g_xh[(size_t)B_ * T_ * C_];
__device__ __nv_bfloat16 g_xl[(size_t)B_ * T_ * C_];
__device__ __nv_bfloat16 g_yh[(size_t)B_ * T_ * C_];
__device__ __nv_bfloat16 g_yl[(size_t)B_ * T_ * C_];
__device__ __nv_bfloat16 g_wah[(size_t)3 * C_ * C_];         // W_attn^T [3C, C]
__device__ __nv_bfloat16 g_wal[(size_t)3 * C_ * C_];
__device__ __nv_bfloat16 g_wph[(size_t)C_ * C_];             // W_proj^T [C, C]
__device__ __nv_bfloat16 g_wpl[(size_t)C_ * C_];

// ---------------------------------------------------------------------------
// mma.sync / ldmatrix / cp.async helpers
// ---------------------------------------------------------------------------
__device__ __forceinline__ uint32_t smem_to_u32(const void* smem_ptr) {
    uint32_t addr;
    asm("{ .reg .u64 tmp; cvta.to.shared.u64 tmp, %1; cvt.u32.u64 %0, tmp; }"
        : "=r"(addr) : "l"(smem_ptr));
    return addr;
}
__device__ __forceinline__ void cp16(uint32_t saddr, const void* g) {
    asm volatile("cp.async.cg.shared.global [%0], [%1], 16;" :: "r"(saddr), "l"(g));
}
__device__ __forceinline__ void cp_commit() {
    asm volatile("cp.async.commit_group;" ::: "memory");
}
template <int N>
__device__ __forceinline__ void cp_wait() {
    asm volatile("cp.async.wait_group %0;" :: "n"(N) : "memory");
}
__device__ __forceinline__ void ldm4(uint32_t* r, uint32_t addr) {
    asm volatile("ldmatrix.sync.aligned.m8n8.x4.shared.b16 {%0,%1,%2,%3}, [%4];"
        : "=r"(r[0]), "=r"(r[1]), "=r"(r[2]), "=r"(r[3]) : "r"(addr));
}
__device__ __forceinline__ void ldm4t(uint32_t* r, uint32_t addr) {
    asm volatile("ldmatrix.sync.aligned.m8n8.x4.trans.shared.b16 {%0,%1,%2,%3}, [%4];"
        : "=r"(r[0]), "=r"(r[1]), "=r"(r[2]), "=r"(r[3]) : "r"(addr));
}
__device__ __forceinline__ void mma_bf16(float* c, const uint32_t* a, const uint32_t* b) {
    asm volatile("mma.sync.aligned.m16n8k16.row.col.f32.bf16.bf16.f32 "
        "{%0,%1,%2,%3}, {%4,%5,%6,%7}, {%8,%9}, {%0,%1,%2,%3};"
        : "+f"(c[0]), "+f"(c[1]), "+f"(c[2]), "+f"(c[3])
        : "r"(a[0]), "r"(a[1]), "r"(a[2]), "r"(a[3]), "r"(b[0]), "r"(b[1]));
}
__device__ __forceinline__ uint32_t pack_bf16(float lo, float hi) {
    __nv_bfloat162 t = __floats2bfloat162_rn(lo, hi);
    return *reinterpret_cast<uint32_t*>(&t);
}
__device__ __forceinline__ void store_split_pair(__nv_bfloat16* Ch, __nv_bfloat16* Cl,
                                                 size_t idx, float v0, float v1) {
    __nv_bfloat162 h = __floats2bfloat162_rn(v0, v1);
    __nv_bfloat162 l = __floats2bfloat162_rn(v0 - __bfloat162float(h.x),
                                             v1 - __bfloat162float(h.y));
    *reinterpret_cast<__nv_bfloat162*>(Ch + idx) = h;
    *reinterpret_cast<__nv_bfloat162*>(Cl + idx) = l;
}

// ---------------------------------------------------------------------------
// Split-precision conversion kernels
// ---------------------------------------------------------------------------
__global__ __launch_bounds__(256) void split_convert(const float* __restrict__ in,
                                                     __nv_bfloat16* __restrict__ oh,
                                                     __nv_bfloat16* __restrict__ ol,
                                                     int n2)
{
    int i = blockIdx.x * blockDim.x + threadIdx.x;
    if (i >= n2) return;
    float2 v = reinterpret_cast<const float2*>(in)[i];
    __nv_bfloat16 hx = __float2bfloat16(v.x);
    __nv_bfloat16 hy = __float2bfloat16(v.y);
    __nv_bfloat162 th; th.x = hx; th.y = hy;
    __nv_bfloat162 tl;
    tl.x = __float2bfloat16(v.x - __bfloat162float(hx));
    tl.y = __float2bfloat16(v.y - __bfloat162float(hy));
    reinterpret_cast<__nv_bfloat162*>(oh)[i] = th;
    reinterpret_cast<__nv_bfloat162*>(ol)[i] = tl;
}

// in: [K,N] fp32 row-major -> out hi/lo: [N,K] bf16 (transposed, K-major)
__global__ __launch_bounds__(256) void transpose_split(const float* __restrict__ in,
                                                       __nv_bfloat16* __restrict__ oh,
                                                       __nv_bfloat16* __restrict__ ol,
                                                       int K, int N)
{
    __shared__ float t[32][33];
    const int nt = blockIdx.x * 32;
    const int kt = blockIdx.y * 32;
    const int tx = threadIdx.x & 31;
    const int ty = threadIdx.x >> 5;
#pragma unroll
    for (int j = 0; j < 4; j++) {
        int k = kt + ty + j * 8;
        t[ty + j * 8][tx] = in[(size_t)k * N + nt + tx];
    }
    __syncthreads();
#pragma unroll
    for (int j = 0; j < 4; j++) {
        int n = nt + ty + j * 8;
        int k = kt + tx;
        float v = t[tx][ty + j * 8];
        __nv_bfloat16 h = __float2bfloat16(v);
        oh[(size_t)n * K + k] = h;
        ol[(size_t)n * K + k] = __float2bfloat16(v - __bfloat162float(h));
    }
}

// ---------------------------------------------------------------------------
// gemm v2: CTA 128x256, 8 warps (2M x 4N), warp tile 64x64, BK=32,
// 3-stage cp.async, single __syncthreads per chunk, 1 CTA/SM.
// C = (Ah+Al) @ (Bh+Bl)^T, 3-product split-bf16, fp32 accum.
// SPLIT_OUT=1: write split bf16 hi/lo; else fp32.
// ---------------------------------------------------------------------------
#define G2_BK 32
#define G2_LDA 40
#define G2_AT (128 * G2_LDA * 2)             // 10240
#define G2_BT (256 * G2_LDA * 2)             // 20480
#define G2_OAH 0
#define G2_OAL G2_AT
#define G2_OBH (2 * G2_AT)
#define G2_OBL (2 * G2_AT + G2_BT)
#define G2_STAGE (2 * G2_AT + 2 * G2_BT)     // 61440
#define G2_SMEM (3 * G2_STAGE)               // 184320

template <int SPLIT_OUT>
__global__ __launch_bounds__(256, 1) void gemm_mma2(
    const __nv_bfloat16* __restrict__ Ah, const __nv_bfloat16* __restrict__ Al,
    const __nv_bfloat16* __restrict__ Bh, const __nv_bfloat16* __restrict__ Bl,
    float* __restrict__ C, __nv_bfloat16* __restrict__ Ch,
    __nv_bfloat16* __restrict__ Cl, int M, int N, int K)
{
    extern __shared__ char smem[];
    const uint32_t sbase = smem_to_u32(smem);

    const int tid  = threadIdx.x;
    const int lane = tid & 31;
    const int wid  = tid >> 5;
    const int warpRow = wid & 1;     // 2 in M
    const int warpCol = wid >> 1;    // 4 in N
    const int m0 = blockIdx.y * 128;
    const int n0 = blockIdx.x * 256;
    const int NC = K / G2_BK;

    // global->smem mapping (16B vectors of 8 bf16)
    const int ar = tid >> 2, as = tid & 3;          // A: 512 vec, 2/thread
    const uint32_t a_soff = (uint32_t)(ar * G2_LDA + as * 8) * 2;

    float acc[4][8][4];
#pragma unroll
    for (int mt = 0; mt < 4; mt++)
#pragma unroll
        for (int f = 0; f < 8; f++)
#pragma unroll
            for (int e = 0; e < 4; e++) acc[mt][f][e] = 0.0f;

    auto load_stage = [&](int stg, int kk) {
        const uint32_t sb = sbase + stg * G2_STAGE;
        // A hi/lo: rows 0..127, 4 segs; vec v = tid + i*256 (i=0,1)
#pragma unroll
        for (int i = 0; i < 2; i++) {
            const int v = tid + i * 256;
            const int row = v >> 2, seg = v & 3;
            const size_t g = (size_t)(m0 + row) * K + kk + seg * 8;
            const uint32_t so = (uint32_t)(row * G2_LDA + seg * 8) * 2;
            cp16(sb + G2_OAH + so, Ah + g);
            cp16(sb + G2_OAL + so, Al + g);
        }
        // B hi/lo: rows 0..255
#pragma unroll
        for (int i = 0; i < 4; i++) {
            const int v = tid + i * 256;
            const int row = v >> 2, seg = v & 3;
            const size_t g = (size_t)(n0 + row) * K + kk + seg * 8;
            const uint32_t so = (uint32_t)(row * G2_LDA + seg * 8) * 2;
            cp16(sb + G2_OBH + so, Bh + g);
            cp16(sb + G2_OBL + so, Bl + g);
        }
        cp_commit();
    };

    load_stage(0, 0);
    load_stage(1, G2_BK);

    const uint32_t a_row = (uint32_t)(warpRow * 64 + (lane & 15));
    const uint32_t a_kof = (uint32_t)((lane >> 4) << 3);
    const uint32_t b_rbase = (uint32_t)(warpCol * 64 + (lane & 7) + ((lane & 16) >> 1));
    const uint32_t b_kof = (uint32_t)(lane & 8);

    for (int c = 0; c < NC; c++) {
        __syncthreads();   // all warps done with buffer (c-1)%3 == (c+2)%3
        if (c + 2 < NC) load_stage((c + 2) % 3, (c + 2) * G2_BK);
        else            cp_commit();
        cp_wait<2>();      // stage c complete

        const uint32_t sb = sbase + (c % 3) * G2_STAGE;

#pragma unroll
        for (int ks = 0; ks < 2; ks++) {
            uint32_t fAh[4][4], fAl[4][4];
#pragma unroll
            for (int mt = 0; mt < 4; mt++) {
                const uint32_t off = ((a_row + mt * 16) * G2_LDA + ks * 16 + a_kof) * 2;
                ldm4(fAh[mt], sb + G2_OAH + off);
                ldm4(fAl[mt], sb + G2_OAL + off);
            }
#pragma unroll
            for (int g = 0; g < 4; g++) {
                uint32_t bh[4], bl[4];
                const uint32_t off = ((b_rbase + g * 16) * G2_LDA + ks * 16 + b_kof) * 2;
                ldm4(bh, sb + G2_OBH + off);
                ldm4(bl, sb + G2_OBL + off);
#pragma unroll
                for (int mt = 0; mt < 4; mt++) {
                    mma_bf16(acc[mt][g * 2],     fAh[mt], bh);
                    mma_bf16(acc[mt][g * 2],     fAh[mt], bl);
                    mma_bf16(acc[mt][g * 2],     fAl[mt], bh);
                    mma_bf16(acc[mt][g * 2 + 1], fAh[mt], bh + 2);
                    mma_bf16(acc[mt][g * 2 + 1], fAh[mt], bl + 2);
                    mma_bf16(acc[mt][g * 2 + 1], fAl[mt], bh + 2);
                }
            }
        }
    }

    // epilogue
    const int erow = m0 + warpRow * 64 + (lane >> 2);
    const int ecol = n0 + warpCol * 64 + (lane & 3) * 2;
#pragma unroll
    for (int mt = 0; mt < 4; mt++) {
#pragma unroll
        for (int f = 0; f < 8; f++) {
            const size_t i0 = (size_t)(erow + mt * 16) * N + ecol + f * 8;
            const size_t i1 = (size_t)(erow + mt * 16 + 8) * N + ecol + f * 8;
            if (SPLIT_OUT) {
                store_split_pair(Ch, Cl, i0, acc[mt][f][0], acc[mt][f][1]);
                store_split_pair(Ch, Cl, i1, acc[mt][f][2], acc[mt][f][3]);
            } else {
                *reinterpret_cast<float2*>(C + i0) = make_float2(acc[mt][f][0], acc[mt][f][1]);
                *reinterpret_cast<float2*>(C + i1) = make_float2(acc[mt][f][2], acc[mt][f][3]);
            }
        }
    }
}

// ---------------------------------------------------------------------------
// Tensor-core SWA flash attention; consumes pre-split qkv hi/lo, emits split y.
// ---------------------------------------------------------------------------
#define SWA_LDT 72
#define SWA_TILE_B (64 * SWA_LDT * 2)     // 9216
#define SWA_SMEM (6 * SWA_TILE_B)         // 55296

__global__ __launch_bounds__(128, 3) void swa_mma(const __nv_bfloat16* __restrict__ qh,
                                                  const __nv_bfloat16* __restrict__ ql,
                                                  __nv_bfloat16* __restrict__ yh,
                                                  __nv_bfloat16* __restrict__ yl)
{
    extern __shared__ char sm[];
    const uint32_t sb = smem_to_u32(sm);
    const uint32_t QH = sb;
    const uint32_t QL = sb + 1 * SWA_TILE_B;
    const uint32_t KH = sb + 2 * SWA_TILE_B;
    const uint32_t KL = sb + 3 * SWA_TILE_B;
    const uint32_t VH = sb + 4 * SWA_TILE_B;
    const uint32_t VL = sb + 5 * SWA_TILE_B;

    const int qt   = blockIdx.x;
    const int h    = blockIdx.y;
    const int b    = blockIdx.z;
    const int tid  = threadIdx.x;
    const int lane = tid & 31;
    const int w    = tid >> 5;

    const size_t st = 3 * C_;
    const __nv_bfloat16* baseh = qh + (size_t)b * T_ * st + (size_t)h * HS_;
    const __nv_bfloat16* basel = ql + (size_t)b * T_ * st + (size_t)h * HS_;

    // --- Q tile: straight hi/lo copies (64 rows x 8 segs of 8 bf16) ---
    for (int it = tid; it < 512; it += 128) {
        const int r   = it >> 3;
        const int sgo = (it & 7) * 8;
        const size_t g = (size_t)(qt * 64 + r) * st + sgo;
        const uint32_t off = (uint32_t)(r * SWA_LDT + sgo) * 2;
        *reinterpret_cast<uint4*>(sm + (QH - sb) + off) =
            *reinterpret_cast<const uint4*>(baseh + g);
        *reinterpret_cast<uint4*>(sm + (QL - sb) + off) =
            *reinterpret_cast<const uint4*>(basel + g);
    }

    float o[8][4];
#pragma unroll
    for (int nt = 0; nt < 8; nt++)
#pragma unroll
        for (int e = 0; e < 4; e++) o[nt][e] = 0.0f;
    float mrow[2] = {-1e30f, -1e30f};
    float lrow[2] = {0.0f, 0.0f};

    const int ig0 = qt * 64 + w * 16 + (lane >> 2);
    const int ig1 = ig0 + 8;
    const int lo_q  = qt * 64 - (WIN_ - 1);
    const int kt_lo = lo_q > 0 ? (lo_q >> 6) : 0;

    for (int kt = kt_lo; kt <= qt; kt++) {
        __syncthreads();
        for (int it = tid; it < 512; it += 128) {
            const int r   = it >> 3;
            const int sgo = (it & 7) * 8;
            const size_t g = (size_t)(kt * 64 + r) * st + sgo;
            const uint32_t off = (uint32_t)(r * SWA_LDT + sgo) * 2;
            *reinterpret_cast<uint4*>(sm + (KH - sb) + off) =
                *reinterpret_cast<const uint4*>(baseh + C_ + g);
            *reinterpret_cast<uint4*>(sm + (KL - sb) + off) =
                *reinterpret_cast<const uint4*>(basel + C_ + g);
            *reinterpret_cast<uint4*>(sm + (VH - sb) + off) =
                *reinterpret_cast<const uint4*>(baseh + 2 * C_ + g);
            *reinterpret_cast<uint4*>(sm + (VL - sb) + off) =
                *reinterpret_cast<const uint4*>(basel + 2 * C_ + g);
        }
        __syncthreads();

        // --- S = Q @ K^T ---
        float s[8][4];
#pragma unroll
        for (int nt = 0; nt < 8; nt++)
#pragma unroll
            for (int e = 0; e < 4; e++) s[nt][e] = 0.0f;

#pragma unroll
        for (int ks = 0; ks < 4; ks++) {
            uint32_t qfh[4], qfl[4];
            const uint32_t aoff =
                (uint32_t)((w * 16 + (lane & 15)) * SWA_LDT + ks * 16 + ((lane >> 4) << 3)) * 2;
            ldm4(qfh, QH + aoff);
            ldm4(qfl, QL + aoff);
#pragma unroll
            for (int jc = 0; jc < 4; jc++) {
                uint32_t kh[4], kl[4];
                const uint32_t boff =
                    (uint32_t)((jc * 16 + (lane & 7) + ((lane & 16) >> 1)) * SWA_LDT
                               + ks * 16 + (lane & 8)) * 2;
                ldm4(kh, KH + boff);
                ldm4(kl, KL + boff);
                mma_bf16(s[jc * 2],     qfh, kh);
                mma_bf16(s[jc * 2],     qfh, kl);
                mma_bf16(s[jc * 2],     qfl, kh);
                mma_bf16(s[jc * 2 + 1], qfh, kh + 2);
                mma_bf16(s[jc * 2 + 1], qfh, kl + 2);
                mma_bf16(s[jc * 2 + 1], qfl, kh + 2);
            }
        }

        // --- masked online softmax ---
        const float sc = 0.125f;
        const int jb = kt * 64 + 2 * (lane & 3);
        float tmax0 = -1e30f, tmax1 = -1e30f;
#pragma unroll
        for (int nt = 0; nt < 8; nt++) {
            const int j0 = jb + nt * 8, j1 = j0 + 1;
            const bool v00 = (j0 <= ig0) && (ig0 - j0 < WIN_);
            const bool v01 = (j1 <= ig0) && (ig0 - j1 < WIN_);
            const bool v10 = (j0 <= ig1) && (ig1 - j0 < WIN_);
            const bool v11 = (j1 <= ig1) && (ig1 - j1 < WIN_);
            s[nt][0] *= sc; s[nt][1] *= sc; s[nt][2] *= sc; s[nt][3] *= sc;
            if (v00) tmax0 = fmaxf(tmax0, s[nt][0]);
            if (v01) tmax0 = fmaxf(tmax0, s[nt][1]);
            if (v10) tmax1 = fmaxf(tmax1, s[nt][2]);
            if (v11) tmax1 = fmaxf(tmax1, s[nt][3]);
        }
        tmax0 = fmaxf(tmax0, __shfl_xor_sync(0xffffffffu, tmax0, 1));
        tmax0 = fmaxf(tmax0, __shfl_xor_sync(0xffffffffu, tmax0, 2));
        tmax1 = fmaxf(tmax1, __shfl_xor_sync(0xffffffffu, tmax1, 1));
        tmax1 = fmaxf(tmax1, __shfl_xor_sync(0xffffffffu, tmax1, 2));

        const float mn0 = fmaxf(mrow[0], tmax0);
        const float mn1 = fmaxf(mrow[1], tmax1);
        const float es0 = __expf(mrow[0] - mn0);
        const float es1 = __expf(mrow[1] - mn1);
        mrow[0] = mn0; mrow[1] = mn1;

        uint32_t ph01[8], ph23[8], pl01[8], pl23[8];
        float ps0 = 0.0f, ps1 = 0.0f;
#pragma unroll
        for (int nt = 0; nt < 8; nt++) {
            const int j0 = jb + nt * 8, j1 = j0 + 1;
            const bool v00 = (j0 <= ig0) && (ig0 - j0 < WIN_);
            const bool v01 = (j1 <= ig0) && (ig0 - j1 < WIN_);
            const bool v10 = (j0 <= ig1) && (ig1 - j0 < WIN_);
            const bool v11 = (j1 <= ig1) && (ig1 - j1 < WIN_);
            const float p00 = v00 ? __expf(s[nt][0] - mn0) : 0.0f;
            const float p01 = v01 ? __expf(s[nt][1] - mn0) : 0.0f;
            const float p10 = v10 ? __expf(s[nt][2] - mn1) : 0.0f;
            const float p11 = v11 ? __expf(s[nt][3] - mn1) : 0.0f;
            ps0 += p00 + p01;
            ps1 += p10 + p11;
            __nv_bfloat162 h01 = __floats2bfloat162_rn(p00, p01);
            __nv_bfloat162 h23 = __floats2bfloat162_rn(p10, p11);
            ph01[nt] = *reinterpret_cast<uint32_t*>(&h01);
            ph23[nt] = *reinterpret_cast<uint32_t*>(&h23);
            pl01[nt] = pack_bf16(p00 - __bfloat162float(h01.x),
                                 p01 - __bfloat162float(h01.y));
            pl23[nt] = pack_bf16(p10 - __bfloat162float(h23.x),
                                 p11 - __bfloat162float(h23.y));
        }
        ps0 += __shfl_xor_sync(0xffffffffu, ps0, 1);
        ps0 += __shfl_xor_sync(0xffffffffu, ps0, 2);
        ps1 += __shfl_xor_sync(0xffffffffu, ps1, 1);
        ps1 += __shfl_xor_sync(0xffffffffu, ps1, 2);
        lrow[0] = lrow[0] * es0 + ps0;
        lrow[1] = lrow[1] * es1 + ps1;
#pragma unroll
        for (int nt = 0; nt < 8; nt++) {
            o[nt][0] *= es0; o[nt][1] *= es0;
            o[nt][2] *= es1; o[nt][3] *= es1;
        }

        // --- O += P @ V ---
#pragma unroll
        for (int kj = 0; kj < 4; kj++) {
            uint32_t ah[4] = {ph01[2 * kj], ph23[2 * kj], ph01[2 * kj + 1], ph23[2 * kj + 1]};
            uint32_t al[4] = {pl01[2 * kj], pl23[2 * kj], pl01[2 * kj + 1], pl23[2 * kj + 1]};
#pragma unroll
            for (int dc = 0; dc < 4; dc++) {
                uint32_t vh[4], vl[4];
                const uint32_t voff =
                    (uint32_t)((kj * 16 + (lane & 15)) * SWA_LDT
                               + dc * 16 + ((lane >> 4) << 3)) * 2;
                ldm4t(vh, VH + voff);
                ldm4t(vl, VL + voff);
                mma_bf16(o[dc * 2],     ah, vh);
                mma_bf16(o[dc * 2],     ah, vl);
                mma_bf16(o[dc * 2],     al, vh);
                mma_bf16(o[dc * 2 + 1], ah, vh + 2);
                mma_bf16(o[dc * 2 + 1], ah, vl + 2);
                mma_bf16(o[dc * 2 + 1], al, vh + 2);
            }
        }
    }

    // --- normalize + write split y ---
    const float inv0 = 1.0f / lrow[0];
    const float inv1 = 1.0f / lrow[1];
    const size_t row0 = (size_t)b * T_ + qt * 64 + w * 16 + (lane >> 2);
    const int    colb = h * HS_ + 2 * (lane & 3);
#pragma unroll
    for (int nt = 0; nt < 8; nt++) {
        store_split_pair(yh, yl, row0 * C_ + colb + nt * 8,
                         o[nt][0] * inv0, o[nt][1] * inv0);
        store_split_pair(yh, yl, (row0 + 8) * C_ + colb + nt * 8,
                         o[nt][2] * inv1, o[nt][3] * inv1);
    }
}

// ---------------------------------------------------------------------------
extern "C" void kernel_launch(void* const* d_in, const int* in_sizes, int n_in,
                              void* d_out, int out_size)
{
    const float* x      = (const float*)d_in[0];
    const float* W_attn = (const float*)d_in[1];
    const float* W_proj = (const float*)d_in[2];
    float* out = (float*)d_out;

    __nv_bfloat16 *qkvh, *qkvl, *xh, *xl, *yh, *yl, *wah, *wal, *wph, *wpl;
    cudaGetSymbolAddress((void**)&qkvh, g_qkvh);
    cudaGetSymbolAddress((void**)&qkvl, g_qkvl);
    cudaGetSymbolAddress((void**)&xh,  g_xh);
    cudaGetSymbolAddress((void**)&xl,  g_xl);
    cudaGetSymbolAddress((void**)&yh,  g_yh);
    cudaGetSymbolAddress((void**)&yl,  g_yl);
    cudaGetSymbolAddress((void**)&wah, g_wah);
    cudaGetSymbolAddress((void**)&wal, g_wal);
    cudaGetSymbolAddress((void**)&wph, g_wph);
    cudaGetSymbolAddress((void**)&wpl, g_wpl);

    cudaFuncSetAttribute(gemm_mma2<0>, cudaFuncAttributeMaxDynamicSharedMemorySize,
                         G2_SMEM);
    cudaFuncSetAttribute(gemm_mma2<1>, cudaFuncAttributeMaxDynamicSharedMemorySize,
                         G2_SMEM);
    cudaFuncSetAttribute(swa_mma, cudaFuncAttributeMaxDynamicSharedMemorySize,
                         SWA_SMEM);

    const int M = B_ * T_;   // 4096

    split_convert<<<(M * C_ / 2 + 255) / 256, 256>>>(x, xh, xl, M * C_ / 2);
    {
        dim3 g(3 * C_ / 32, C_ / 32);
        transpose_split<<<g, 256>>>(W_attn, wah, wal, C_, 3 * C_);
    }
    {
        dim3 g(C_ / 32, C_ / 32);
        transpose_split<<<g, 256>>>(W_proj, wph, wpl, C_, C_);
    }

    // qkv(split) = x @ W_attn  (M=4096, N=3072, K=1024)
    {
        dim3 g(3 * C_ / 256, M / 128);
        gemm_mma2<1><<<g, 256, G2_SMEM>>>(xh, xl, wah, wal,
                                          nullptr, qkvh, qkvl, M, 3 * C_, C_);
    }

    // fused SWA -> split y
    {
        dim3 g(T_ / 64, NH_, B_);
        swa_mma<<<g, 128, SWA_SMEM>>>(qkvh, qkvl, yh, yl);
    }

    // out = y @ W_proj  (M=4096, N=1024, K=1024)
    {
        dim3 g(C_ / 256, M / 128);
        gemm_mma2<0><<<g, 256, G2_SMEM>>>(yh, yl, wph, wpl,
                                          out, nullptr, nullptr, M, C_, C_);
    }
}